// round 1
// baseline (speedup 1.0000x reference)
#include <cuda_runtime.h>
#include <cuda_fp16.h>
#include <cstdint>

#define M_TOTAL 2048
#define K_TOTAL 4096
#define N_TOTAL 11008
#define GROUPSZ 128
#define NPACK   (N_TOTAL / 8)   // 1376
#define NGROUPS (K_TOTAL / GROUPSZ)

// Scratch (allocation-free rules: __device__ globals)
__device__ __half g_W[(size_t)K_TOTAL * N_TOTAL];   // ~90 MB fp16 dequantized weights [K][N]
__device__ __half g_X[(size_t)M_TOTAL * K_TOTAL];   // ~16 MB fp16 activations [M][K]

// ---------------------------------------------------------------------------
// Kernel 1: dequantize packed int4 -> fp16.  One thread per packed int32 word.
// w[k][np*8+j] = ((qw>>(4j))&0xF - (qz>>(4j))&0xF) * scales[g][np*8+j]
// ---------------------------------------------------------------------------
__global__ void dequant_kernel(const int* __restrict__ qweight,
                               const int* __restrict__ qzeros,
                               const float* __restrict__ scales) {
    int idx = blockIdx.x * blockDim.x + threadIdx.x;
    if (idx >= K_TOTAL * NPACK) return;
    int k  = idx / NPACK;
    int np = idx - k * NPACK;
    int g  = k / GROUPSZ;

    uint32_t qw = ((const uint32_t*)qweight)[idx];
    uint32_t qz = ((const uint32_t*)qzeros)[g * NPACK + np];
    const float4* s4 = (const float4*)(scales + (size_t)g * N_TOTAL + np * 8);
    float4 s0 = s4[0];
    float4 s1 = s4[1];
    float s[8] = {s0.x, s0.y, s0.z, s0.w, s1.x, s1.y, s1.z, s1.w};

    __half w[8];
#pragma unroll
    for (int j = 0; j < 8; j++) {
        float wv = (float)((qw >> (4 * j)) & 0xF);
        float zv = (float)((qz >> (4 * j)) & 0xF);
        w[j] = __float2half((wv - zv) * s[j]);
    }
    *(uint4*)(&g_W[(size_t)k * N_TOTAL + np * 8]) = *(uint4*)w;
}

// ---------------------------------------------------------------------------
// Kernel 2: convert x fp32 -> fp16.  8 elements per thread.
// ---------------------------------------------------------------------------
__global__ void convert_x_kernel(const float* __restrict__ x) {
    int idx = blockIdx.x * blockDim.x + threadIdx.x;
    if (idx >= M_TOTAL * K_TOTAL / 8) return;
    const float4* xv = (const float4*)x;
    float4 f0 = xv[idx * 2 + 0];
    float4 f1 = xv[idx * 2 + 1];
    __half2 h[4];
    h[0] = __floats2half2_rn(f0.x, f0.y);
    h[1] = __floats2half2_rn(f0.z, f0.w);
    h[2] = __floats2half2_rn(f1.x, f1.y);
    h[3] = __floats2half2_rn(f1.z, f1.w);
    *(uint4*)(&g_X[(size_t)idx * 8]) = *(uint4*)h;
}

// ---------------------------------------------------------------------------
// Kernel 3: GEMM  out[M,N] = X[M,K] * W[K,N] + bias
// fp16 mma.sync.m16n8k16, fp32 accum. BM=128 BN=128 BK=32, 8 warps (2Mx4N),
// warp tile 64x32.  cp.async double-buffered smem, padded for conflict-free
// ldmatrix (A stride 40 halves = 80B, B stride 136 halves = 272B).
// ---------------------------------------------------------------------------
#define BM 128
#define BN 128
#define BK 32
#define LDA_S 40
#define LDB_S 136
#define KT (K_TOTAL / BK)   // 128

__device__ __forceinline__ uint32_t smem_u32(const void* p) {
    return (uint32_t)__cvta_generic_to_shared(p);
}

__device__ __forceinline__ void cp_async_16(uint32_t saddr, const void* gaddr) {
    asm volatile("cp.async.cg.shared.global [%0], [%1], 16;\n" :: "r"(saddr), "l"(gaddr));
}

__global__ void __launch_bounds__(256, 2) gemm_kernel(const float* __restrict__ bias,
                                                      float* __restrict__ out) {
    __shared__ __half As[2][BM * LDA_S];   // 2*128*40*2  = 20480 B
    __shared__ __half Bs[2][BK * LDB_S];   // 2*32*136*2  = 17408 B

    const int tid  = threadIdx.x;
    const int lane = tid & 31;
    const int warp = tid >> 5;
    const int warp_m = warp & 1;   // 0..1 -> 64 rows each
    const int warp_n = warp >> 1;  // 0..3 -> 32 cols each
    const int bn = blockIdx.x;     // N tile
    const int bm = blockIdx.y;     // M tile

    // global load mapping
    const int a_row = tid >> 2;          // 0..63 (two iters: +0, +64)
    const int a_chk = (tid & 3) * 8;     // half offset within row
    const int b_row = tid >> 4;          // 0..15 (two iters: +0, +16)
    const int b_chk = (tid & 15) * 8;

    const __half* gA = g_X + (size_t)(bm * BM) * K_TOTAL;
    const __half* gB = g_W + (size_t)(bn * BN);

    float acc[4][4][4];
#pragma unroll
    for (int i = 0; i < 4; i++)
#pragma unroll
        for (int j = 0; j < 4; j++)
#pragma unroll
            for (int c = 0; c < 4; c++) acc[i][j][c] = 0.f;

    // prologue: load stage 0
    {
        const int k0 = 0;
#pragma unroll
        for (int it = 0; it < 2; it++) {
            int r = a_row + it * 64;
            cp_async_16(smem_u32(&As[0][r * LDA_S + a_chk]),
                        gA + (size_t)r * K_TOTAL + k0 + a_chk);
        }
#pragma unroll
        for (int it = 0; it < 2; it++) {
            int r = b_row + it * 16;
            cp_async_16(smem_u32(&Bs[0][r * LDB_S + b_chk]),
                        gB + (size_t)(k0 + r) * N_TOTAL + b_chk);
        }
        asm volatile("cp.async.commit_group;\n" ::);
    }

    int buf = 0;
    for (int kt = 0; kt < KT; kt++) {
        if (kt + 1 < KT) {
            const int k0 = (kt + 1) * BK;
            const int nb = buf ^ 1;
#pragma unroll
            for (int it = 0; it < 2; it++) {
                int r = a_row + it * 64;
                cp_async_16(smem_u32(&As[nb][r * LDA_S + a_chk]),
                            gA + (size_t)r * K_TOTAL + k0 + a_chk);
            }
#pragma unroll
            for (int it = 0; it < 2; it++) {
                int r = b_row + it * 16;
                cp_async_16(smem_u32(&Bs[nb][r * LDB_S + b_chk]),
                            gB + (size_t)(k0 + r) * N_TOTAL + b_chk);
            }
            asm volatile("cp.async.commit_group;\n" ::);
            asm volatile("cp.async.wait_group 1;\n" ::);
        } else {
            asm volatile("cp.async.wait_group 0;\n" ::);
        }
        __syncthreads();

        const uint32_t a_base = smem_u32(&As[buf][0]);
        const uint32_t b_base = smem_u32(&Bs[buf][0]);

#pragma unroll
        for (int k16 = 0; k16 < 2; k16++) {
            uint32_t a[4][4];
            uint32_t b[4][2];
#pragma unroll
            for (int mt = 0; mt < 4; mt++) {
                int row = warp_m * 64 + mt * 16 + (lane & 15);
                int col = k16 * 16 + (lane >> 4) * 8;
                uint32_t addr = a_base + (uint32_t)(row * LDA_S + col) * 2u;
                asm volatile("ldmatrix.sync.aligned.m8n8.x4.shared.b16 {%0,%1,%2,%3}, [%4];"
                             : "=r"(a[mt][0]), "=r"(a[mt][1]), "=r"(a[mt][2]), "=r"(a[mt][3])
                             : "r"(addr));
            }
#pragma unroll
            for (int nt = 0; nt < 4; nt++) {
                int row = k16 * 16 + (lane & 15);
                int col = warp_n * 32 + nt * 8;
                uint32_t addr = b_base + (uint32_t)(row * LDB_S + col) * 2u;
                asm volatile("ldmatrix.sync.aligned.m8n8.x2.trans.shared.b16 {%0,%1}, [%2];"
                             : "=r"(b[nt][0]), "=r"(b[nt][1])
                             : "r"(addr));
            }
#pragma unroll
            for (int mt = 0; mt < 4; mt++) {
#pragma unroll
                for (int nt = 0; nt < 4; nt++) {
                    asm volatile(
                        "mma.sync.aligned.m16n8k16.row.col.f32.f16.f16.f32 "
                        "{%0,%1,%2,%3}, {%4,%5,%6,%7}, {%8,%9}, {%0,%1,%2,%3};"
                        : "+f"(acc[mt][nt][0]), "+f"(acc[mt][nt][1]),
                          "+f"(acc[mt][nt][2]), "+f"(acc[mt][nt][3])
                        : "r"(a[mt][0]), "r"(a[mt][1]), "r"(a[mt][2]), "r"(a[mt][3]),
                          "r"(b[nt][0]), "r"(b[nt][1]));
                }
            }
        }
        __syncthreads();
        buf ^= 1;
    }

    // epilogue: add bias, store fp32
    const int row0 = bm * BM + warp_m * 64 + (lane >> 2);
    const int col0 = bn * BN + warp_n * 32 + (lane & 3) * 2;
#pragma unroll
    for (int mt = 0; mt < 4; mt++) {
#pragma unroll
        for (int nt = 0; nt < 4; nt++) {
            int col = col0 + nt * 8;
            float2 bv = *(const float2*)&bias[col];
            int r0 = row0 + mt * 16;
            float2 v0 = {acc[mt][nt][0] + bv.x, acc[mt][nt][1] + bv.y};
            float2 v1 = {acc[mt][nt][2] + bv.x, acc[mt][nt][3] + bv.y};
            *(float2*)&out[(size_t)r0 * N_TOTAL + col] = v0;
            *(float2*)&out[(size_t)(r0 + 8) * N_TOTAL + col] = v1;
        }
    }
}

// ---------------------------------------------------------------------------
extern "C" void kernel_launch(void* const* d_in, const int* in_sizes, int n_in,
                              void* d_out, int out_size) {
    const float* x       = (const float*)d_in[0];
    const int*   qweight = (const int*)d_in[1];
    const int*   qzeros  = (const int*)d_in[2];
    const float* scales  = (const float*)d_in[3];
    const float* bias    = (const float*)d_in[4];
    float*       out     = (float*)d_out;

    dequant_kernel<<<(K_TOTAL * NPACK + 255) / 256, 256>>>(qweight, qzeros, scales);
    convert_x_kernel<<<(M_TOTAL * K_TOTAL / 8 + 255) / 256, 256>>>(x);
    gemm_kernel<<<dim3(N_TOTAL / BN, M_TOTAL / BM), 256>>>(bias, out);
}